// round 2
// baseline (speedup 1.0000x reference)
#include <cuda_runtime.h>
#include <cstdint>

#define C_DIM  256
#define NCODES 256
#define HW_DIM (128 * 256)   // 32768
#define BATCH  4

// Precomputed projection matrix M (stored TF32-rounded) and inverse norms.
__device__ float d_inv_norm[NCODES];
__device__ float d_M[C_DIM * C_DIM];

// ---------------------------------------------------------------------------
// Kernel 0: inv_norm[n] = 1 / sum_c cb[n][c]^2
// ---------------------------------------------------------------------------
__global__ void norm_kernel(const float* __restrict__ cb) {
    int n = blockIdx.x;
    int c = threadIdx.x;
    float v = cb[n * C_DIM + c];
    float s = v * v;
    #pragma unroll
    for (int off = 16; off; off >>= 1) s += __shfl_xor_sync(0xffffffffu, s, off);
    __shared__ float ws[8];
    if ((c & 31) == 0) ws[c >> 5] = s;
    __syncthreads();
    if (c < 8) {
        float t = ws[c];
        #pragma unroll
        for (int off = 4; off; off >>= 1) t += __shfl_xor_sync(0xffu, t, off);
        if (c == 0) d_inv_norm[n] = 1.0f / t;
    }
}

// ---------------------------------------------------------------------------
// Kernel 1: M[i][j] = sum_n cb[n][i] * cb[n][j] * inv_norm[n]   (TF32-rounded)
// Grid (16,16): each block one 16x16 tile of M. Block = 256 threads.
// ---------------------------------------------------------------------------
__global__ void mmat_kernel(const float* __restrict__ cb) {
    __shared__ float sI[NCODES][16];
    __shared__ float sJ[NCODES][16];
    const int I0 = blockIdx.x * 16, J0 = blockIdx.y * 16;
    const int tid = threadIdx.x;

    for (int e = tid; e < NCODES * 16; e += 256) {
        int n = e >> 4, ii = e & 15;
        sI[n][ii] = cb[n * C_DIM + I0 + ii];
        sJ[n][ii] = cb[n * C_DIM + J0 + ii] * d_inv_norm[n];
    }
    __syncthreads();

    const int ti = tid & 15, tj = tid >> 4;
    float acc = 0.0f;
    #pragma unroll 8
    for (int n = 0; n < NCODES; n++) acc += sI[n][ti] * sJ[n][tj];

    uint32_t r;
    asm("cvt.rna.tf32.f32 %0, %1;" : "=r"(r) : "f"(acc));
    d_M[(I0 + ti) * C_DIM + (J0 + tj)] = __uint_as_float(r);
}

// ---------------------------------------------------------------------------
// Kernel 2: out[b][c][p] = sum_k M[c][k] * feat[b][k][p]
// CTA tile: 256(M) x 64(N), K-block 32, double-buffered smem, TF32 mma.sync.
// Grid (HW/64, B), 256 threads (8 warps: 4 along M x 2 along N).
// ---------------------------------------------------------------------------
#define AS_STRIDE 36            // words; 36 % 32 == 4 -> conflict-free A frags
#define AS_SIZE   (256 * AS_STRIDE)
#define BS_STRIDE 72            // words; 72 % 32 == 8 -> conflict-free B frags
#define BS_SIZE   (32 * BS_STRIDE)
#define SMEM_FLOATS (2 * AS_SIZE + 2 * BS_SIZE)
#define SMEM_BYTES  (SMEM_FLOATS * 4)

__device__ __forceinline__ float to_tf32(float x) {
    uint32_t u;
    asm("cvt.rna.tf32.f32 %0, %1;" : "=r"(u) : "f"(x));
    return __uint_as_float(u);
}

__device__ __forceinline__ void mma_tf32(float c[4],
                                         uint32_t a0, uint32_t a1, uint32_t a2, uint32_t a3,
                                         uint32_t b0, uint32_t b1) {
    asm volatile(
        "mma.sync.aligned.m16n8k8.row.col.f32.tf32.tf32.f32 "
        "{%0,%1,%2,%3}, {%4,%5,%6,%7}, {%8,%9}, {%0,%1,%2,%3};"
        : "+f"(c[0]), "+f"(c[1]), "+f"(c[2]), "+f"(c[3])
        : "r"(a0), "r"(a1), "r"(a2), "r"(a3), "r"(b0), "r"(b1));
}

__device__ __forceinline__ void cp_async16(uint32_t smem_addr, const void* gptr) {
    asm volatile("cp.async.cg.shared.global [%0], [%1], 16;" :: "r"(smem_addr), "l"(gptr));
}
__device__ __forceinline__ void cp_commit() {
    asm volatile("cp.async.commit_group;");
}
__device__ __forceinline__ void cp_wait_all() {
    asm volatile("cp.async.wait_group 0;");
}

__global__ void __launch_bounds__(256, 2)
gemm_kernel(const float* __restrict__ feat, float* __restrict__ out) {
    extern __shared__ float smem[];
    float* As = smem;                    // 2 buffers of [256][AS_STRIDE]
    float* Bs = smem + 2 * AS_SIZE;      // 2 buffers of [32][BS_STRIDE]

    const int tid  = threadIdx.x;
    const int lane = tid & 31;
    const int warp = tid >> 5;
    const int g    = lane >> 2;          // groupID
    const int tg   = lane & 3;           // thread-in-group
    const int wm   = warp & 3;           // warp M index (x64)
    const int wn   = warp >> 2;          // warp N index (x32)

    const int p0 = blockIdx.x * 64;
    const int b  = blockIdx.y;
    const float* Bg = feat + (size_t)b * C_DIM * HW_DIM + p0;

    // A loader mapping: 8 float4 per thread per K-block
    const int a_mrow = tid >> 3;          // 0..31 (+ pass*32)
    const int a_kq   = tid & 7;           // float4 index within 32-wide K block
    // B loader mapping: 2 float4 per thread per K-block
    const int b_krow = tid >> 4;          // 0..15 (+ pass*16)
    const int b_pq   = tid & 15;          // float4 index within 64-wide N block

    const uint32_t as_base = (uint32_t)__cvta_generic_to_shared(As);
    float acc[4][4][4];
    #pragma unroll
    for (int mi = 0; mi < 4; mi++)
        #pragma unroll
        for (int ni = 0; ni < 4; ni++)
            #pragma unroll
            for (int q = 0; q < 4; q++) acc[mi][ni][q] = 0.0f;

    // ---- prologue: load K-block 0 into buffer 0 ----
    {
        #pragma unroll
        for (int pass = 0; pass < 8; pass++) {
            int m = a_mrow + pass * 32;
            cp_async16(as_base + (uint32_t)(m * AS_STRIDE + a_kq * 4) * 4,
                       d_M + m * C_DIM + a_kq * 4);
        }
        cp_commit();
        float4 v0 = *(const float4*)(Bg + (size_t)b_krow * HW_DIM + b_pq * 4);
        float4 v1 = *(const float4*)(Bg + (size_t)(b_krow + 16) * HW_DIM + b_pq * 4);
        float* dst0 = Bs + b_krow * BS_STRIDE + b_pq * 4;
        float* dst1 = Bs + (b_krow + 16) * BS_STRIDE + b_pq * 4;
        dst0[0] = to_tf32(v0.x); dst0[1] = to_tf32(v0.y);
        dst0[2] = to_tf32(v0.z); dst0[3] = to_tf32(v0.w);
        dst1[0] = to_tf32(v1.x); dst1[1] = to_tf32(v1.y);
        dst1[2] = to_tf32(v1.z); dst1[3] = to_tf32(v1.w);
        cp_wait_all();
    }
    __syncthreads();

    #pragma unroll
    for (int kb = 0; kb < 8; kb++) {
        const int cur = kb & 1;
        const int nxt = cur ^ 1;
        float4 rb0, rb1;

        if (kb < 7) {
            // prefetch A(kb+1) via cp.async into the other buffer
            #pragma unroll
            for (int pass = 0; pass < 8; pass++) {
                int m = a_mrow + pass * 32;
                cp_async16(as_base + (uint32_t)(nxt * AS_SIZE + m * AS_STRIDE + a_kq * 4) * 4,
                           d_M + m * C_DIM + (kb + 1) * 32 + a_kq * 4);
            }
            cp_commit();
            // prefetch B(kb+1) into registers
            const float* Bsrc = Bg + (size_t)((kb + 1) * 32) * HW_DIM;
            rb0 = *(const float4*)(Bsrc + (size_t)b_krow * HW_DIM + b_pq * 4);
            rb1 = *(const float4*)(Bsrc + (size_t)(b_krow + 16) * HW_DIM + b_pq * 4);
        }

        // ---- compute on buffer cur ----
        const float* Asb = As + cur * AS_SIZE;
        const float* Bsb = Bs + cur * BS_SIZE;
        #pragma unroll
        for (int kk = 0; kk < 4; kk++) {
            const int k0 = kk * 8;
            uint32_t a[4][4];
            #pragma unroll
            for (int mi = 0; mi < 4; mi++) {
                int r0 = wm * 64 + mi * 16 + g;
                a[mi][0] = __float_as_uint(Asb[r0 * AS_STRIDE + k0 + tg]);
                a[mi][1] = __float_as_uint(Asb[(r0 + 8) * AS_STRIDE + k0 + tg]);
                a[mi][2] = __float_as_uint(Asb[r0 * AS_STRIDE + k0 + tg + 4]);
                a[mi][3] = __float_as_uint(Asb[(r0 + 8) * AS_STRIDE + k0 + tg + 4]);
            }
            uint32_t bf[4][2];
            #pragma unroll
            for (int ni = 0; ni < 4; ni++) {
                int nn = wn * 32 + ni * 8 + g;
                bf[ni][0] = __float_as_uint(Bsb[(k0 + tg) * BS_STRIDE + nn]);
                bf[ni][1] = __float_as_uint(Bsb[(k0 + tg + 4) * BS_STRIDE + nn]);
            }
            #pragma unroll
            for (int mi = 0; mi < 4; mi++)
                #pragma unroll
                for (int ni = 0; ni < 4; ni++)
                    mma_tf32(acc[mi][ni], a[mi][0], a[mi][1], a[mi][2], a[mi][3],
                             bf[ni][0], bf[ni][1]);
        }

        if (kb < 7) {
            // stage B(kb+1) into the other buffer (with TF32 rounding)
            float* dst0 = Bs + nxt * BS_SIZE + b_krow * BS_STRIDE + b_pq * 4;
            float* dst1 = Bs + nxt * BS_SIZE + (b_krow + 16) * BS_STRIDE + b_pq * 4;
            dst0[0] = to_tf32(rb0.x); dst0[1] = to_tf32(rb0.y);
            dst0[2] = to_tf32(rb0.z); dst0[3] = to_tf32(rb0.w);
            dst1[0] = to_tf32(rb1.x); dst1[1] = to_tf32(rb1.y);
            dst1[2] = to_tf32(rb1.z); dst1[3] = to_tf32(rb1.w);
            cp_wait_all();
            __syncthreads();
        }
    }

    // ---- epilogue: 32B-sector-aligned float2 stores ----
    float* Og = out + (size_t)b * C_DIM * HW_DIM + p0;
    #pragma unroll
    for (int mi = 0; mi < 4; mi++) {
        int c0 = wm * 64 + mi * 16 + g;
        #pragma unroll
        for (int ni = 0; ni < 4; ni++) {
            int p = wn * 32 + ni * 8 + 2 * tg;
            float2 v01 = make_float2(acc[mi][ni][0], acc[mi][ni][1]);
            float2 v23 = make_float2(acc[mi][ni][2], acc[mi][ni][3]);
            *(float2*)(Og + (size_t)c0 * HW_DIM + p) = v01;
            *(float2*)(Og + (size_t)(c0 + 8) * HW_DIM + p) = v23;
        }
    }
}

// ---------------------------------------------------------------------------
extern "C" void kernel_launch(void* const* d_in, const int* in_sizes, int n_in,
                              void* d_out, int out_size) {
    const float* feat = (const float*)d_in[0];   // [B, C, H, W] fp32
    const float* cb   = (const float*)d_in[1];   // [N, C] fp32
    float* out        = (float*)d_out;           // [B, C, H, W] fp32

    norm_kernel<<<NCODES, C_DIM>>>(cb);
    mmat_kernel<<<dim3(16, 16), 256>>>(cb);

    cudaFuncSetAttribute(gemm_kernel,
                         cudaFuncAttributeMaxDynamicSharedMemorySize, SMEM_BYTES);
    gemm_kernel<<<dim3(HW_DIM / 64, BATCH), 256, SMEM_BYTES>>>(feat, out);
}

// round 3
// speedup vs baseline: 1.0149x; 1.0149x over previous
#include <cuda_runtime.h>
#include <cstdint>

#define C_DIM  256
#define NCODES 256
#define HW_DIM (128 * 256)   // 32768
#define BATCH  4

// Precomputed projection matrix M (stored TF32-rounded) and inverse norms.
__device__ float d_inv_norm[NCODES];
__device__ float d_M[C_DIM * C_DIM];

// ---------------------------------------------------------------------------
// Kernel 0: inv_norm[n] = 1 / sum_c cb[n][c]^2
// ---------------------------------------------------------------------------
__global__ void norm_kernel(const float* __restrict__ cb) {
    int n = blockIdx.x;
    int c = threadIdx.x;
    float v = cb[n * C_DIM + c];
    float s = v * v;
    #pragma unroll
    for (int off = 16; off; off >>= 1) s += __shfl_xor_sync(0xffffffffu, s, off);
    __shared__ float ws[8];
    if ((c & 31) == 0) ws[c >> 5] = s;
    __syncthreads();
    if (c < 8) {
        float t = ws[c];
        #pragma unroll
        for (int off = 4; off; off >>= 1) t += __shfl_xor_sync(0xffu, t, off);
        if (c == 0) d_inv_norm[n] = 1.0f / t;
    }
}

// ---------------------------------------------------------------------------
// Kernel 1: M[i][j] = sum_n cb[n][i] * cb[n][j] * inv_norm[n]   (TF32-rounded)
// Grid (16,16): each block one 16x16 tile of M. Block = 256 threads.
// ---------------------------------------------------------------------------
__global__ void mmat_kernel(const float* __restrict__ cb) {
    __shared__ float sI[NCODES][16];
    __shared__ float sJ[NCODES][16];
    const int I0 = blockIdx.x * 16, J0 = blockIdx.y * 16;
    const int tid = threadIdx.x;

    for (int e = tid; e < NCODES * 16; e += 256) {
        int n = e >> 4, ii = e & 15;
        sI[n][ii] = cb[n * C_DIM + I0 + ii];
        sJ[n][ii] = cb[n * C_DIM + J0 + ii] * d_inv_norm[n];
    }
    __syncthreads();

    const int ti = tid & 15, tj = tid >> 4;
    float acc = 0.0f;
    #pragma unroll 8
    for (int n = 0; n < NCODES; n++) acc += sI[n][ti] * sJ[n][tj];

    uint32_t r;
    asm("cvt.rna.tf32.f32 %0, %1;" : "=r"(r) : "f"(acc));
    d_M[(I0 + ti) * C_DIM + (J0 + tj)] = __uint_as_float(r);
}

// ---------------------------------------------------------------------------
// Kernel 2: out[b][c][p] = sum_k M[c][k] * feat[b][k][p]
// CTA tile: 256(M) x 64(N), K-block 32, double-buffered smem, TF32 mma.sync.
// Grid (HW/64, B), 256 threads (8 warps: 4 along M x 2 along N).
// ---------------------------------------------------------------------------
#define AS_STRIDE 36            // words; 36 % 32 == 4 -> conflict-free A frags
#define AS_SIZE   (256 * AS_STRIDE)
#define BS_STRIDE 72            // words; 72 % 32 == 8 -> conflict-free B frags
#define BS_SIZE   (32 * BS_STRIDE)
#define SMEM_FLOATS (2 * AS_SIZE + 2 * BS_SIZE)
#define SMEM_BYTES  (SMEM_FLOATS * 4)

__device__ __forceinline__ float to_tf32(float x) {
    uint32_t u;
    asm("cvt.rna.tf32.f32 %0, %1;" : "=r"(u) : "f"(x));
    return __uint_as_float(u);
}

__device__ __forceinline__ void mma_tf32(float c[4],
                                         uint32_t a0, uint32_t a1, uint32_t a2, uint32_t a3,
                                         uint32_t b0, uint32_t b1) {
    asm volatile(
        "mma.sync.aligned.m16n8k8.row.col.f32.tf32.tf32.f32 "
        "{%0,%1,%2,%3}, {%4,%5,%6,%7}, {%8,%9}, {%0,%1,%2,%3};"
        : "+f"(c[0]), "+f"(c[1]), "+f"(c[2]), "+f"(c[3])
        : "r"(a0), "r"(a1), "r"(a2), "r"(a3), "r"(b0), "r"(b1));
}

__device__ __forceinline__ void cp_async16(uint32_t smem_addr, const void* gptr) {
    asm volatile("cp.async.cg.shared.global [%0], [%1], 16;" :: "r"(smem_addr), "l"(gptr));
}
__device__ __forceinline__ void cp_commit() {
    asm volatile("cp.async.commit_group;");
}
__device__ __forceinline__ void cp_wait_all() {
    asm volatile("cp.async.wait_group 0;");
}

__global__ void __launch_bounds__(256, 2)
gemm_kernel(const float* __restrict__ feat, float* __restrict__ out) {
    extern __shared__ float smem[];
    float* As = smem;                    // 2 buffers of [256][AS_STRIDE]
    float* Bs = smem + 2 * AS_SIZE;      // 2 buffers of [32][BS_STRIDE]

    const int tid  = threadIdx.x;
    const int lane = tid & 31;
    const int warp = tid >> 5;
    const int g    = lane >> 2;          // groupID
    const int tg   = lane & 3;           // thread-in-group
    const int wm   = warp & 3;           // warp M index (x64)
    const int wn   = warp >> 2;          // warp N index (x32)

    const int p0 = blockIdx.x * 64;
    const int b  = blockIdx.y;
    const float* Bg = feat + (size_t)b * C_DIM * HW_DIM + p0;

    // A loader mapping: 8 float4 per thread per K-block
    const int a_mrow = tid >> 3;          // 0..31 (+ pass*32)
    const int a_kq   = tid & 7;           // float4 index within 32-wide K block
    // B loader mapping: 2 float4 per thread per K-block
    const int b_krow = tid >> 4;          // 0..15 (+ pass*16)
    const int b_pq   = tid & 15;          // float4 index within 64-wide N block

    const uint32_t as_base = (uint32_t)__cvta_generic_to_shared(As);
    float acc[4][4][4];
    #pragma unroll
    for (int mi = 0; mi < 4; mi++)
        #pragma unroll
        for (int ni = 0; ni < 4; ni++)
            #pragma unroll
            for (int q = 0; q < 4; q++) acc[mi][ni][q] = 0.0f;

    // ---- prologue: load K-block 0 into buffer 0 ----
    {
        #pragma unroll
        for (int pass = 0; pass < 8; pass++) {
            int m = a_mrow + pass * 32;
            cp_async16(as_base + (uint32_t)(m * AS_STRIDE + a_kq * 4) * 4,
                       d_M + m * C_DIM + a_kq * 4);
        }
        cp_commit();
        float4 v0 = *(const float4*)(Bg + (size_t)b_krow * HW_DIM + b_pq * 4);
        float4 v1 = *(const float4*)(Bg + (size_t)(b_krow + 16) * HW_DIM + b_pq * 4);
        float* dst0 = Bs + b_krow * BS_STRIDE + b_pq * 4;
        float* dst1 = Bs + (b_krow + 16) * BS_STRIDE + b_pq * 4;
        dst0[0] = to_tf32(v0.x); dst0[1] = to_tf32(v0.y);
        dst0[2] = to_tf32(v0.z); dst0[3] = to_tf32(v0.w);
        dst1[0] = to_tf32(v1.x); dst1[1] = to_tf32(v1.y);
        dst1[2] = to_tf32(v1.z); dst1[3] = to_tf32(v1.w);
        cp_wait_all();
    }
    __syncthreads();

    #pragma unroll
    for (int kb = 0; kb < 8; kb++) {
        const int cur = kb & 1;
        const int nxt = cur ^ 1;
        float4 rb0, rb1;

        if (kb < 7) {
            // prefetch A(kb+1) via cp.async into the other buffer
            #pragma unroll
            for (int pass = 0; pass < 8; pass++) {
                int m = a_mrow + pass * 32;
                cp_async16(as_base + (uint32_t)(nxt * AS_SIZE + m * AS_STRIDE + a_kq * 4) * 4,
                           d_M + m * C_DIM + (kb + 1) * 32 + a_kq * 4);
            }
            cp_commit();
            // prefetch B(kb+1) into registers
            const float* Bsrc = Bg + (size_t)((kb + 1) * 32) * HW_DIM;
            rb0 = *(const float4*)(Bsrc + (size_t)b_krow * HW_DIM + b_pq * 4);
            rb1 = *(const float4*)(Bsrc + (size_t)(b_krow + 16) * HW_DIM + b_pq * 4);
        }

        // ---- compute on buffer cur ----
        const float* Asb = As + cur * AS_SIZE;
        const float* Bsb = Bs + cur * BS_SIZE;
        #pragma unroll
        for (int kk = 0; kk < 4; kk++) {
            const int k0 = kk * 8;
            uint32_t a[4][4];
            #pragma unroll
            for (int mi = 0; mi < 4; mi++) {
                int r0 = wm * 64 + mi * 16 + g;
                a[mi][0] = __float_as_uint(Asb[r0 * AS_STRIDE + k0 + tg]);
                a[mi][1] = __float_as_uint(Asb[(r0 + 8) * AS_STRIDE + k0 + tg]);
                a[mi][2] = __float_as_uint(Asb[r0 * AS_STRIDE + k0 + tg + 4]);
                a[mi][3] = __float_as_uint(Asb[(r0 + 8) * AS_STRIDE + k0 + tg + 4]);
            }
            uint32_t bf[4][2];
            #pragma unroll
            for (int ni = 0; ni < 4; ni++) {
                int nn = wn * 32 + ni * 8 + g;
                bf[ni][0] = __float_as_uint(Bsb[(k0 + tg) * BS_STRIDE + nn]);
                bf[ni][1] = __float_as_uint(Bsb[(k0 + tg + 4) * BS_STRIDE + nn]);
            }
            #pragma unroll
            for (int mi = 0; mi < 4; mi++)
                #pragma unroll
                for (int ni = 0; ni < 4; ni++)
                    mma_tf32(acc[mi][ni], a[mi][0], a[mi][1], a[mi][2], a[mi][3],
                             bf[ni][0], bf[ni][1]);
        }

        if (kb < 7) {
            // stage B(kb+1) into the other buffer (with TF32 rounding)
            float* dst0 = Bs + nxt * BS_SIZE + b_krow * BS_STRIDE + b_pq * 4;
            float* dst1 = Bs + nxt * BS_SIZE + (b_krow + 16) * BS_STRIDE + b_pq * 4;
            dst0[0] = to_tf32(rb0.x); dst0[1] = to_tf32(rb0.y);
            dst0[2] = to_tf32(rb0.z); dst0[3] = to_tf32(rb0.w);
            dst1[0] = to_tf32(rb1.x); dst1[1] = to_tf32(rb1.y);
            dst1[2] = to_tf32(rb1.z); dst1[3] = to_tf32(rb1.w);
            cp_wait_all();
            __syncthreads();
        }
    }

    // ---- epilogue: 32B-sector-aligned float2 stores ----
    float* Og = out + (size_t)b * C_DIM * HW_DIM + p0;
    #pragma unroll
    for (int mi = 0; mi < 4; mi++) {
        int c0 = wm * 64 + mi * 16 + g;
        #pragma unroll
        for (int ni = 0; ni < 4; ni++) {
            int p = wn * 32 + ni * 8 + 2 * tg;
            float2 v01 = make_float2(acc[mi][ni][0], acc[mi][ni][1]);
            float2 v23 = make_float2(acc[mi][ni][2], acc[mi][ni][3]);
            *(float2*)(Og + (size_t)c0 * HW_DIM + p) = v01;
            *(float2*)(Og + (size_t)(c0 + 8) * HW_DIM + p) = v23;
        }
    }
}

// ---------------------------------------------------------------------------
extern "C" void kernel_launch(void* const* d_in, const int* in_sizes, int n_in,
                              void* d_out, int out_size) {
    const float* feat = (const float*)d_in[0];   // [B, C, H, W] fp32
    const float* cb   = (const float*)d_in[1];   // [N, C] fp32
    float* out        = (float*)d_out;           // [B, C, H, W] fp32

    norm_kernel<<<NCODES, C_DIM>>>(cb);
    mmat_kernel<<<dim3(16, 16), 256>>>(cb);

    cudaFuncSetAttribute(gemm_kernel,
                         cudaFuncAttributeMaxDynamicSharedMemorySize, SMEM_BYTES);
    gemm_kernel<<<dim3(HW_DIM / 64, BATCH), 256, SMEM_BYTES>>>(feat, out);
}